// round 12
// baseline (speedup 1.0000x reference)
#include <cuda_runtime.h>
#include <cuda_bf16.h>
#include <math.h>
#include <stdint.h>

// Problem constants
#define BATCH 32
#define NNODE 1024
#define FEAT  256           // IN_F == OUT_F == 256
#define MROWS (BATCH*NNODE) // 32768
#define ALPHA_LRELU 0.2f

// ---------------- scratch (device globals; no runtime allocation) -----------
// WhT: o-major per batch, node index PERMUTED within each 8-group by
// ptab = [0,2,4,6,1,3,5,7]  (so logical k and k+4 are storage-adjacent)
__device__ float  g_WhT[(size_t)BATCH * FEAT * NNODE];       // 32 MB
__device__ double g_si[MROWS];
__device__ double g_sj[MROWS];

// ---------------- helpers ----------------------------------------------------
__device__ __forceinline__ float to_tf32(float x) {
    float r;
    asm("cvt.rna.tf32.f32 %0, %1;" : "=f"(r) : "f"(x));
    return r;
}

__device__ __forceinline__ void cp16(uint32_t dst, const void* src) {
    asm volatile("cp.async.cg.shared.global [%0], [%1], 16;\n" :: "r"(dst), "l"(src));
}
__device__ __forceinline__ void cp_commit() {
    asm volatile("cp.async.commit_group;\n" ::);
}
__device__ __forceinline__ void cp_wait1() {
    asm volatile("cp.async.wait_group 1;\n" ::);
}
__device__ __forceinline__ void cp_wait0() {
    asm volatile("cp.async.wait_group 0;\n" ::);
}

__device__ __forceinline__ void mma_tf32(float* c, const uint32_t* a, const uint32_t* b) {
    asm volatile(
        "mma.sync.aligned.m16n8k8.row.col.f32.tf32.tf32.f32 "
        "{%0,%1,%2,%3}, {%4,%5,%6,%7}, {%8,%9}, {%0,%1,%2,%3};"
        : "+f"(c[0]), "+f"(c[1]), "+f"(c[2]), "+f"(c[3])
        : "r"(a[0]), "r"(a[1]), "r"(a[2]), "r"(a[3]), "r"(b[0]), "r"(b[1]));
}

// ============================================================================
// K1: Wh[m,o] = sum_k h[m,k] * W[o,k]   (NT GEMM, M=32768, N=256, K=256)
// tf32 mma with rna cvt on fragments (proven numerics), 128x128 tile, BK=16.
// Epilogue: writes o-major node-PERMUTED g_WhT + si/sj double atomics.
// ============================================================================
__global__ __launch_bounds__(256, 2) void k_wh_tc(const float* __restrict__ A,
                                                  const float* __restrict__ Bw,
                                                  const float* __restrict__ avec)
{
    __shared__ float sA[2][128][20];
    __shared__ float sW[2][128][20];

    const int m0 = blockIdx.y * 128;
    const int n0 = blockIdx.x * 128;
    const int tid  = threadIdx.x;
    const int lane = tid & 31;
    const int wid  = tid >> 5;
    const int m0w  = (wid >> 2) * 64;   // 0 or 64
    const int n0w  = (wid & 3) * 32;    // 0,32,64,96

    float acc[4][4][4];
#pragma unroll
    for (int i = 0; i < 4; i++)
#pragma unroll
        for (int j = 0; j < 4; j++)
#pragma unroll
            for (int r = 0; r < 4; r++) acc[i][j][r] = 0.f;

    const int T = FEAT / 16;  // 16

    auto load_stage = [&](int buf, int k0) {
#pragma unroll
        for (int it = 0; it < 2; it++) {
            int f   = tid + it * 256;    // 0..511
            int row = f >> 2;
            int kq  = (f & 3) * 4;
            cp16((uint32_t)__cvta_generic_to_shared(&sA[buf][row][kq]),
                 A + (size_t)(m0 + row) * FEAT + k0 + kq);
            cp16((uint32_t)__cvta_generic_to_shared(&sW[buf][row][kq]),
                 Bw + (size_t)(n0 + row) * FEAT + k0 + kq);
        }
    };

    load_stage(0, 0);
    cp_commit();

    for (int t = 0; t < T; t++) {
        if (t + 1 < T) { load_stage((t + 1) & 1, (t + 1) * 16); cp_commit(); }
        if (t + 1 < T) cp_wait1(); else cp_wait0();
        __syncthreads();

        const int buf = t & 1;
#pragma unroll
        for (int kk = 0; kk < 16; kk += 8) {
            uint32_t a[4][4];
#pragma unroll
            for (int mi = 0; mi < 4; mi++) {
                int r = m0w + mi * 16 + (lane >> 2);
                a[mi][0] = __float_as_uint(to_tf32(sA[buf][r    ][kk + (lane & 3)    ]));
                a[mi][1] = __float_as_uint(to_tf32(sA[buf][r + 8][kk + (lane & 3)    ]));
                a[mi][2] = __float_as_uint(to_tf32(sA[buf][r    ][kk + (lane & 3) + 4]));
                a[mi][3] = __float_as_uint(to_tf32(sA[buf][r + 8][kk + (lane & 3) + 4]));
            }
            uint32_t bf[4][2];
#pragma unroll
            for (int nj = 0; nj < 4; nj++) {
                int c = n0w + nj * 8 + (lane >> 2);
                bf[nj][0] = __float_as_uint(to_tf32(sW[buf][c][kk + (lane & 3)    ]));
                bf[nj][1] = __float_as_uint(to_tf32(sW[buf][c][kk + (lane & 3) + 4]));
            }
#pragma unroll
            for (int mi = 0; mi < 4; mi++)
#pragma unroll
                for (int nj = 0; nj < 4; nj++)
                    mma_tf32(acc[mi][nj], a[mi], bf[nj]);
        }
        __syncthreads();
    }

    // preload a1/a2 for this thread's 8 columns
    float a1v[8], a2v[8];
#pragma unroll
    for (int nj = 0; nj < 4; nj++) {
        int c = n0 + n0w + nj * 8 + 2 * (lane & 3);
        a1v[nj * 2]     = avec[c];
        a1v[nj * 2 + 1] = avec[c + 1];
        a2v[nj * 2]     = avec[FEAT + c];
        a2v[nj * 2 + 1] = avec[FEAT + c + 1];
    }

    // permuted node position within 8-group: ptab[j] = (j<4) ? 2j : 2j-7
    const int j3 = lane >> 2;                 // row & 7
    const int pj3 = (j3 < 4) ? (2 * j3) : (2 * j3 - 7);

#pragma unroll
    for (int mi = 0; mi < 4; mi++) {
        int row = m0 + m0w + mi * 16 + (lane >> 2);
        int nl  = row & 1023;                        // node within batch
        int pr  = (nl & ~7) | pj3;                   // permuted node
        size_t bb = (size_t)(row >> 10) * ((size_t)FEAT * NNODE);
        float p1_lo = 0.f, p2_lo = 0.f, p1_hi = 0.f, p2_hi = 0.f;
#pragma unroll
        for (int nj = 0; nj < 4; nj++) {
            int col = n0 + n0w + nj * 8 + 2 * (lane & 3);
            float v0 = to_tf32(acc[mi][nj][0]);
            float v1 = to_tf32(acc[mi][nj][1]);
            float v2 = to_tf32(acc[mi][nj][2]);
            float v3 = to_tf32(acc[mi][nj][3]);
            g_WhT[bb + (size_t)col * NNODE + pr]           = v0;
            g_WhT[bb + (size_t)(col + 1) * NNODE + pr]     = v1;
            g_WhT[bb + (size_t)col * NNODE + pr + 8]       = v2;
            g_WhT[bb + (size_t)(col + 1) * NNODE + pr + 8] = v3;
            p1_lo += v0 * a1v[nj * 2] + v1 * a1v[nj * 2 + 1];
            p2_lo += v0 * a2v[nj * 2] + v1 * a2v[nj * 2 + 1];
            p1_hi += v2 * a1v[nj * 2] + v3 * a1v[nj * 2 + 1];
            p2_hi += v2 * a2v[nj * 2] + v3 * a2v[nj * 2 + 1];
        }
        p1_lo += __shfl_xor_sync(0xffffffff, p1_lo, 1);
        p1_lo += __shfl_xor_sync(0xffffffff, p1_lo, 2);
        p2_lo += __shfl_xor_sync(0xffffffff, p2_lo, 1);
        p2_lo += __shfl_xor_sync(0xffffffff, p2_lo, 2);
        p1_hi += __shfl_xor_sync(0xffffffff, p1_hi, 1);
        p1_hi += __shfl_xor_sync(0xffffffff, p1_hi, 2);
        p2_hi += __shfl_xor_sync(0xffffffff, p2_hi, 1);
        p2_hi += __shfl_xor_sync(0xffffffff, p2_hi, 2);
        if ((lane & 3) == 0) {
            atomicAdd(&g_si[row], (double)p1_lo);
            atomicAdd(&g_sj[row], (double)p2_lo);
            atomicAdd(&g_si[row + 8], (double)p1_hi);
            atomicAdd(&g_sj[row + 8], (double)p2_hi);
        }
    }
}

// ============================================================================
// K3 (fused): R8's proven pipeline; operands in k-PERMUTED, 16B-XOR-swizzled
// tiles so each mma (k, k+4) fragment pair is one LDS.64.
//   wh: [n=256][k=32] rows of 128B (from o-major permuted g_WhT)
//   e:  [m=64][k=32] rows of 128B (written permuted+swizzled by compute_e)
// BI=64, BJ=32, 256 threads, 2 CTAs/SM. One __syncthreads per j-step.
// ============================================================================
#define BI 64
#define BJ 32

struct SmemFused {
    float  wh[2][256][32];   // 65536 B  [n][k], XOR-swizzled 16B chunks
    float  e[2][BI][32];     // 16384 B  [m][k], XOR-swizzled 16B chunks
    int    adj[2][BI][BJ];   // 16384 B  (rs aliases adj[0] after the loop)
    float2 pq[NNODE];        // 8192 B   {exp(sj), exp(0.2 sj)}
};                           // total 106,496 B -> 2 CTAs/SM

__global__ __launch_bounds__(256, 2) void k_fused(const int* __restrict__ adj,
                                                  float* __restrict__ out)
{
    extern __shared__ char smem_raw[];
    SmemFused* s = (SmemFused*)smem_raw;

    const int b  = blockIdx.y;
    const int i0 = blockIdx.x * BI;
    const int tid  = threadIdx.x;
    const int lane = tid & 31;
    const int wid  = tid >> 5;
    const int m0w  = (wid >> 2) * 32;   // 0 or 32
    const int n0w  = (wid & 3) * 64;    // 0,64,128,192
    const int k2   = lane & 3;
    const int r7   = lane >> 2;

    const int*   adjb = adj   + ((size_t)b * NNODE + i0) * NNODE;
    const float* WhTb = g_WhT + (size_t)b * FEAT * NNODE;

    // preamble: pq for this batch (4/thread), pi/qi for this row
#pragma unroll
    for (int u = 0; u < 4; u++) {
        int j = tid + u * 256;
        float sjv = (float)g_sj[(size_t)b * NNODE + j];
        s->pq[j] = make_float2(__expf(sjv), __expf(ALPHA_LRELU * sjv));
    }
    const int   erow = tid >> 2;            // E row this thread produces
    const int   ecol = (tid & 3) * 8;       // first of 8 logical E cols
    const float si_r = (float)g_si[(size_t)b * NNODE + i0 + erow];
    const float pi_r = __expf(si_r);
    const float qi_r = __expf(ALPHA_LRELU * si_r);

    float acc[2][8][4];
#pragma unroll
    for (int i = 0; i < 2; i++)
#pragma unroll
        for (int j = 0; j < 8; j++)
#pragma unroll
            for (int r = 0; r < 4; r++) acc[i][j][r] = 0.f;

    float esum = 0.f;

    auto load_adj = [&](int buf, int j0) {
#pragma unroll
        for (int it = 0; it < 2; it++) {
            int f   = tid + it * 256;
            int row = f >> 3;
            int c   = (f & 7) * 4;
            cp16((uint32_t)__cvta_generic_to_shared(&s->adj[buf][row][c]),
                 adjb + (size_t)row * NNODE + j0 + c);
        }
    };
    // wh: 256 o-rows x 32 k (permuted in global); swizzle chunk q -> q^(o&7)
    auto load_wh = [&](int buf, int j0) {
#pragma unroll
        for (int it = 0; it < 8; it++) {
            int f  = tid + it * 256;     // 0..2047
            int o  = f >> 3;
            int qq = f & 7;
            cp16((uint32_t)__cvta_generic_to_shared(
                     (char*)s->wh[buf] + o * 128 + ((qq ^ (o & 7)) << 4)),
                 WhTb + (size_t)o * NNODE + j0 + qq * 4);
        }
    };

    // E tile: logical cols ecol..ecol+7 -> permuted [0,4,1,5 | 2,6,3,7], swizzled
    auto compute_e = [&](int ebuf, int abuf, int j0) {
        float ev[8];
#pragma unroll
        for (int u = 0; u < 8; u++) {
            int jc = ecol + u;
            float2 pqv = s->pq[j0 + jc];
            float ep = pi_r * pqv.x;
            float eq = qi_r * pqv.y;
            float e  = (ep >= 1.0f) ? ep : eq;
            e = (s->adj[abuf][erow][jc] > 0) ? e : 0.f;
            e = __uint_as_float(__float_as_uint(e) & 0xffffe000u);  // tf32 trunc
            esum += e;
            ev[u] = e;
        }
        float4 s0 = make_float4(ev[0], ev[4], ev[1], ev[5]);
        float4 s1 = make_float4(ev[2], ev[6], ev[3], ev[7]);
        char* ebase = (char*)s->e[ebuf] + erow * 128;
        int q0 = ecol >> 2;                         // 0,2,4,6
        *(float4*)(ebase + (((q0    ) ^ (erow & 7)) << 4)) = s0;
        *(float4*)(ebase + (((q0 + 1) ^ (erow & 7)) << 4)) = s1;
    };

    const int T = NNODE / BJ;  // 32

    // ---- Preamble: G_a={adj(0)}, G_0={wh(0), adj(1)} ----
    load_adj(0, 0);
    cp_commit();
    load_wh(0, 0);
    load_adj(1, BJ);
    cp_commit();
    cp_wait1();          // adj(0) arrived
    __syncthreads();     // pq visible

    compute_e(0, 0, 0);
    __syncthreads();     // E(0) visible

    for (int t = 0; t < T; t++) {
        const int buf = t & 1;

        // Commit G_{t+1} = {wh(t+1), adj(t+2)}; wait for G_t = {wh(t), adj(t+1)}
        if (t + 1 < T) {
            load_wh(buf ^ 1, (t + 1) * BJ);
            if (t + 2 < T) load_adj(buf, (t + 2) * BJ);
            cp_commit();
            cp_wait1();
        } else {
            cp_wait0();
        }

        // ---- MMA(t): 64x256 += E(t) @ Wh(t), LDS.64 fragment pairs ----
#pragma unroll
        for (int kk = 0; kk < BJ; kk += 8) {
            const int q   = (kk >> 2) + (k2 >> 1);
            const int off = ((q ^ r7) << 4) + ((k2 & 1) << 3);   // byte offset
            uint32_t a[2][4];
#pragma unroll
            for (int mi = 0; mi < 2; mi++) {
                int r = m0w + mi * 16 + r7;
                float2 v0 = *(const float2*)((const char*)s->e[buf] + r * 128 + off);
                float2 v1 = *(const float2*)((const char*)s->e[buf] + (r + 8) * 128 + off);
                a[mi][0] = __float_as_uint(v0.x);
                a[mi][1] = __float_as_uint(v1.x);
                a[mi][2] = __float_as_uint(v0.y);
                a[mi][3] = __float_as_uint(v1.y);
            }
            uint32_t bf[8][2];
#pragma unroll
            for (int nj = 0; nj < 8; nj++) {
                int c = n0w + nj * 8 + r7;
                float2 v = *(const float2*)((const char*)s->wh[buf] + c * 128 + off);
                bf[nj][0] = __float_as_uint(v.x);
                bf[nj][1] = __float_as_uint(v.y);
            }
#pragma unroll
            for (int mi = 0; mi < 2; mi++)
#pragma unroll
                for (int nj = 0; nj < 8; nj++)
                    mma_tf32(acc[mi][nj], a[mi], bf[nj]);
        }

        // ---- E-compute(t+1) overlaps HMMA drain ----
        if (t + 1 < T) compute_e(buf ^ 1, buf ^ 1, (t + 1) * BJ);

        __syncthreads();   // single barrier per iteration
    }

    // rowsum: rs aliases adj[0] (adj dead after the loop; wait0 drained cp.async)
    float* rs = (float*)&s->adj[0][0][0];
    esum += __shfl_xor_sync(0xffffffff, esum, 1);
    esum += __shfl_xor_sync(0xffffffff, esum, 2);
    if ((tid & 3) == 0) rs[erow] = esum;
    __syncthreads();

    // epilogue: normalize, ELU (expm1f — precise near 0), store
#pragma unroll
    for (int mi = 0; mi < 2; mi++) {
        int r0 = m0w + mi * 16 + r7;
        float inv0 = 1.f / rs[r0];
        float inv1 = 1.f / rs[r0 + 8];
#pragma unroll
        for (int nj = 0; nj < 8; nj++) {
            int col = n0w + nj * 8 + 2 * k2;
            float v0 = acc[mi][nj][0] * inv0, v1 = acc[mi][nj][1] * inv0;
            float v2 = acc[mi][nj][2] * inv1, v3 = acc[mi][nj][3] * inv1;
            v0 = (v0 > 0.f) ? v0 : expm1f(v0);
            v1 = (v1 > 0.f) ? v1 : expm1f(v1);
            v2 = (v2 > 0.f) ? v2 : expm1f(v2);
            v3 = (v3 > 0.f) ? v3 : expm1f(v3);
            size_t base = (size_t)(b * NNODE + i0 + r0) * FEAT + col;
            *(float2*)(out + base)            = make_float2(v0, v1);
            *(float2*)(out + base + 8 * FEAT) = make_float2(v2, v3);
        }
    }
}

// ============================================================================
// launch
// ============================================================================
extern "C" void kernel_launch(void* const* d_in, const int* in_sizes, int n_in,
                              void* d_out, int out_size)
{
    const float* h   = (const float*)d_in[0];
    const int*   adj = (const int*)  d_in[1];
    const float* W   = (const float*)d_in[2];
    const float* a   = (const float*)d_in[3];
    float*       out = (float*)d_out;

    // zero si/sj accumulators (doubles, filled by k_wh_tc epilogue atomics)
    void* p_si = nullptr;
    void* p_sj = nullptr;
    cudaGetSymbolAddress(&p_si, g_si);
    cudaGetSymbolAddress(&p_sj, g_sj);
    cudaMemsetAsync(p_si, 0, MROWS * sizeof(double));
    cudaMemsetAsync(p_sj, 0, MROWS * sizeof(double));

    // K1: WhT = perm(h @ W^T) o-major + si/sj accumulation
    {
        dim3 grid(FEAT / 128, MROWS / 128);   // (2, 256)
        k_wh_tc<<<grid, 256>>>(h, W, a);
    }
    // K3: fused masked-softmax + attn@Wh + ELU (paired-fragment LDS.64)
    {
        cudaFuncSetAttribute(k_fused, cudaFuncAttributeMaxDynamicSharedMemorySize,
                             (int)sizeof(SmemFused));
        dim3 grid(NNODE / BI, BATCH);         // (16, 32)
        k_fused<<<grid, 256, sizeof(SmemFused)>>>(adj, out);
    }
}

// round 13
// speedup vs baseline: 1.1545x; 1.1545x over previous
#include <cuda_runtime.h>
#include <cuda_bf16.h>
#include <math.h>
#include <stdint.h>

// Problem constants
#define BATCH 32
#define NNODE 1024
#define FEAT  256           // IN_F == OUT_F == 256
#define MROWS (BATCH*NNODE) // 32768
#define ALPHA_LRELU 0.2f

// ---------------- scratch (device globals; no runtime allocation) -----------
__device__ float  g_Wh[(size_t)MROWS * FEAT];                // 32 MB (tf32-rounded)
__device__ double g_si[MROWS];
__device__ double g_sj[MROWS];

// ---------------- helpers ----------------------------------------------------
__device__ __forceinline__ float to_tf32(float x) {
    float r;
    asm("cvt.rna.tf32.f32 %0, %1;" : "=f"(r) : "f"(x));
    return r;
}

__device__ __forceinline__ void cp16(uint32_t dst, const void* src) {
    asm volatile("cp.async.cg.shared.global [%0], [%1], 16;\n" :: "r"(dst), "l"(src));
}
__device__ __forceinline__ void cp_commit() {
    asm volatile("cp.async.commit_group;\n" ::);
}
__device__ __forceinline__ void cp_wait1() {
    asm volatile("cp.async.wait_group 1;\n" ::);
}
__device__ __forceinline__ void cp_wait0() {
    asm volatile("cp.async.wait_group 0;\n" ::);
}

__device__ __forceinline__ void mma_tf32(float* c, const uint32_t* a, const uint32_t* b) {
    asm volatile(
        "mma.sync.aligned.m16n8k8.row.col.f32.tf32.tf32.f32 "
        "{%0,%1,%2,%3}, {%4,%5,%6,%7}, {%8,%9}, {%0,%1,%2,%3};"
        : "+f"(c[0]), "+f"(c[1]), "+f"(c[2]), "+f"(c[3])
        : "r"(a[0]), "r"(a[1]), "r"(a[2]), "r"(a[3]), "r"(b[0]), "r"(b[1]));
}

// precise-cheap expm1 for v <= 0: Taylor near 0, expf-1 elsewhere.
__device__ __forceinline__ float elu_neg(float v) {
    float em = __expf(v) - 1.f;
    float ta = v + 0.5f * v * v * (1.f + 0.33333333f * v);   // v + v^2/2 + v^3/6
    return (v > -0.0625f) ? ta : em;
}
__device__ __forceinline__ float elu(float v) {
    return (v > 0.f) ? v : elu_neg(v);
}

// ============================================================================
// K1: Wh[m,o] = sum_k h[m,k] * W[o,k]   (NT GEMM, M=32768, N=256, K=256)
// tf32 mma with rna cvt on fragments (proven numerics), 128x128 tile, BK=16.
// Epilogue accumulates si/sj partials via quad-reduced DOUBLE atomicAdd.
// ============================================================================
__global__ __launch_bounds__(256, 2) void k_wh_tc(const float* __restrict__ A,
                                                  const float* __restrict__ Bw,
                                                  const float* __restrict__ avec)
{
    __shared__ float sA[2][128][20];
    __shared__ float sW[2][128][20];

    const int m0 = blockIdx.y * 128;
    const int n0 = blockIdx.x * 128;
    const int tid  = threadIdx.x;
    const int lane = tid & 31;
    const int wid  = tid >> 5;
    const int m0w  = (wid >> 2) * 64;   // 0 or 64
    const int n0w  = (wid & 3) * 32;    // 0,32,64,96

    float acc[4][4][4];
#pragma unroll
    for (int i = 0; i < 4; i++)
#pragma unroll
        for (int j = 0; j < 4; j++)
#pragma unroll
            for (int r = 0; r < 4; r++) acc[i][j][r] = 0.f;

    const int T = FEAT / 16;  // 16

    auto load_stage = [&](int buf, int k0) {
#pragma unroll
        for (int it = 0; it < 2; it++) {
            int f   = tid + it * 256;    // 0..511
            int row = f >> 2;
            int kq  = (f & 3) * 4;
            cp16((uint32_t)__cvta_generic_to_shared(&sA[buf][row][kq]),
                 A + (size_t)(m0 + row) * FEAT + k0 + kq);
            cp16((uint32_t)__cvta_generic_to_shared(&sW[buf][row][kq]),
                 Bw + (size_t)(n0 + row) * FEAT + k0 + kq);
        }
    };

    load_stage(0, 0);
    cp_commit();

    for (int t = 0; t < T; t++) {
        if (t + 1 < T) { load_stage((t + 1) & 1, (t + 1) * 16); cp_commit(); }
        if (t + 1 < T) cp_wait1(); else cp_wait0();
        __syncthreads();

        const int buf = t & 1;
#pragma unroll
        for (int kk = 0; kk < 16; kk += 8) {
            uint32_t a[4][4];
#pragma unroll
            for (int mi = 0; mi < 4; mi++) {
                int r = m0w + mi * 16 + (lane >> 2);
                a[mi][0] = __float_as_uint(to_tf32(sA[buf][r    ][kk + (lane & 3)    ]));
                a[mi][1] = __float_as_uint(to_tf32(sA[buf][r + 8][kk + (lane & 3)    ]));
                a[mi][2] = __float_as_uint(to_tf32(sA[buf][r    ][kk + (lane & 3) + 4]));
                a[mi][3] = __float_as_uint(to_tf32(sA[buf][r + 8][kk + (lane & 3) + 4]));
            }
            uint32_t bf[4][2];
#pragma unroll
            for (int nj = 0; nj < 4; nj++) {
                int c = n0w + nj * 8 + (lane >> 2);
                bf[nj][0] = __float_as_uint(to_tf32(sW[buf][c][kk + (lane & 3)    ]));
                bf[nj][1] = __float_as_uint(to_tf32(sW[buf][c][kk + (lane & 3) + 4]));
            }
#pragma unroll
            for (int mi = 0; mi < 4; mi++)
#pragma unroll
                for (int nj = 0; nj < 4; nj++)
                    mma_tf32(acc[mi][nj], a[mi], bf[nj]);
        }
        __syncthreads();
    }

    // preload a1/a2 for this thread's 8 columns
    float a1v[8], a2v[8];
#pragma unroll
    for (int nj = 0; nj < 4; nj++) {
        int c = n0 + n0w + nj * 8 + 2 * (lane & 3);
        a1v[nj * 2]     = avec[c];
        a1v[nj * 2 + 1] = avec[c + 1];
        a2v[nj * 2]     = avec[FEAT + c];
        a2v[nj * 2 + 1] = avec[FEAT + c + 1];
    }

#pragma unroll
    for (int mi = 0; mi < 4; mi++) {
        int row = m0 + m0w + mi * 16 + (lane >> 2);
        float p1_lo = 0.f, p2_lo = 0.f, p1_hi = 0.f, p2_hi = 0.f;
#pragma unroll
        for (int nj = 0; nj < 4; nj++) {
            int col = n0 + n0w + nj * 8 + 2 * (lane & 3);
            float v0 = to_tf32(acc[mi][nj][0]);
            float v1 = to_tf32(acc[mi][nj][1]);
            float v2 = to_tf32(acc[mi][nj][2]);
            float v3 = to_tf32(acc[mi][nj][3]);
            *(float2*)(g_Wh + (size_t)row * FEAT + col)       = make_float2(v0, v1);
            *(float2*)(g_Wh + (size_t)(row + 8) * FEAT + col) = make_float2(v2, v3);
            p1_lo += v0 * a1v[nj * 2] + v1 * a1v[nj * 2 + 1];
            p2_lo += v0 * a2v[nj * 2] + v1 * a2v[nj * 2 + 1];
            p1_hi += v2 * a1v[nj * 2] + v3 * a1v[nj * 2 + 1];
            p2_hi += v2 * a2v[nj * 2] + v3 * a2v[nj * 2 + 1];
        }
        // quad reduce (lanes sharing the same rows, different col pairs)
        p1_lo += __shfl_xor_sync(0xffffffff, p1_lo, 1);
        p1_lo += __shfl_xor_sync(0xffffffff, p1_lo, 2);
        p2_lo += __shfl_xor_sync(0xffffffff, p2_lo, 1);
        p2_lo += __shfl_xor_sync(0xffffffff, p2_lo, 2);
        p1_hi += __shfl_xor_sync(0xffffffff, p1_hi, 1);
        p1_hi += __shfl_xor_sync(0xffffffff, p1_hi, 2);
        p2_hi += __shfl_xor_sync(0xffffffff, p2_hi, 1);
        p2_hi += __shfl_xor_sync(0xffffffff, p2_hi, 2);
        if ((lane & 3) == 0) {
            atomicAdd(&g_si[row], (double)p1_lo);
            atomicAdd(&g_sj[row], (double)p2_lo);
            atomicAdd(&g_si[row + 8], (double)p1_hi);
            atomicAdd(&g_sj[row + 8], (double)p2_hi);
        }
    }
}

// ============================================================================
// K3 (fused, pipelined, factorized-exp) — R8's PROVEN shell:
//   E[i,j] = adj ? ( pi*pj >= 1 ? pi*pj : qi*qj ) : 0
//   O[i,:] = (E @ Wh[b]) / rowsum(E), then ELU.
// adj via cp.async smem; vectorized LDS.128 adj/pq reads in compute_e.
// BI=64, BJ=32, 256 threads, 2 CTAs/SM. One __syncthreads per j-step.
// ============================================================================
#define BI 64
#define BJ 32

struct SmemFused {
    float  wh[2][BJ][264];   // [k][n] B tiles
    float  e[2][BI][36];     // E tiles, double-buffered
    int    adj[2][BI][BJ];
    float2 pq[NNODE];        // {exp(sj), exp(0.2 sj)}
    float  rs[BI];
};

__global__ __launch_bounds__(256, 2) void k_fused(const int* __restrict__ adj,
                                                  float* __restrict__ out)
{
    extern __shared__ char smem_raw[];
    SmemFused* s = (SmemFused*)smem_raw;

    const int b  = blockIdx.y;
    const int i0 = blockIdx.x * BI;
    const int tid  = threadIdx.x;
    const int lane = tid & 31;
    const int wid  = tid >> 5;
    const int m0w  = (wid >> 2) * 32;   // 0 or 32
    const int n0w  = (wid & 3) * 64;    // 0,64,128,192

    const int*   adjb = adj  + ((size_t)b * NNODE + i0) * NNODE;
    const float* Whb  = g_Wh + (size_t)b * NNODE * FEAT;

    // preamble: pj/qj for this batch (4 per thread), pi/qi for this row
#pragma unroll
    for (int u = 0; u < 4; u++) {
        int j = tid + u * 256;
        float sjv = (float)g_sj[(size_t)b * NNODE + j];
        s->pq[j] = make_float2(__expf(sjv), __expf(ALPHA_LRELU * sjv));
    }
    const int   erow = tid >> 2;            // E row this thread produces
    const int   ecol = (tid & 3) * 8;       // first of 8 E cols
    const float si_r = (float)g_si[(size_t)b * NNODE + i0 + erow];
    const float pi_r = __expf(si_r);
    const float qi_r = __expf(ALPHA_LRELU * si_r);

    float acc[2][8][4];
#pragma unroll
    for (int i = 0; i < 2; i++)
#pragma unroll
        for (int j = 0; j < 8; j++)
#pragma unroll
            for (int r = 0; r < 4; r++) acc[i][j][r] = 0.f;

    float esum = 0.f;

    auto load_adj = [&](int buf, int j0) {
#pragma unroll
        for (int it = 0; it < 2; it++) {
            int f   = tid + it * 256;
            int row = f >> 3;
            int c   = (f & 7) * 4;
            cp16((uint32_t)__cvta_generic_to_shared(&s->adj[buf][row][c]),
                 adjb + (size_t)row * NNODE + j0 + c);
        }
    };
    auto load_wh = [&](int buf, int j0) {
#pragma unroll
        for (int it = 0; it < 8; it++) {
            int f = tid + it * 256;
            int k = f >> 6;
            int c = (f & 63) * 4;
            cp16((uint32_t)__cvta_generic_to_shared(&s->wh[buf][k][c]),
                 Whb + (size_t)(j0 + k) * FEAT + c);
        }
    };

    // E-tile compute into e[ebuf] from adj[abuf] at column offset j0
    // (vectorized: 2x LDS.128 adj, 4x LDS.128 pq)
    auto compute_e = [&](int ebuf, int abuf, int j0) {
        int4 a0 = *(const int4*)&s->adj[abuf][erow][ecol];
        int4 a1 = *(const int4*)&s->adj[abuf][erow][ecol + 4];
        const float4* pq4 = (const float4*)&s->pq[j0 + ecol];
        float4 q0 = pq4[0], q1 = pq4[1], q2 = pq4[2], q3 = pq4[3];
        const int   am[8]  = { a0.x, a0.y, a0.z, a0.w, a1.x, a1.y, a1.z, a1.w };
        const float pjv[8] = { q0.x, q0.z, q1.x, q1.z, q2.x, q2.z, q3.x, q3.z };
        const float qjv[8] = { q0.y, q0.w, q1.y, q1.w, q2.y, q2.w, q3.y, q3.w };
        float ev[8];
#pragma unroll
        for (int u = 0; u < 8; u++) {
            float ep = pi_r * pjv[u];
            float eq = qi_r * qjv[u];
            float e  = (ep >= 1.0f) ? ep : eq;
            e = (am[u] > 0) ? e : 0.f;
            e = __uint_as_float(__float_as_uint(e) & 0xffffe000u);  // tf32 trunc
            esum += e;
            ev[u] = e;
        }
        *(float4*)&s->e[ebuf][erow][ecol]     = make_float4(ev[0], ev[1], ev[2], ev[3]);
        *(float4*)&s->e[ebuf][erow][ecol + 4] = make_float4(ev[4], ev[5], ev[6], ev[7]);
    };

    const int T = NNODE / BJ;  // 32

    // Preamble: G_a = {adj(0)}, G_0 = {wh(0), adj(1)}
    load_adj(0, 0);
    cp_commit();
    load_wh(0, 0);
    load_adj(1, BJ);
    cp_commit();
    cp_wait1();          // adj(0) arrived
    __syncthreads();     // also publishes pq

    compute_e(0, 0, 0);
    __syncthreads();

    for (int t = 0; t < T; t++) {
        const int buf = t & 1;

        // Commit G_{t+1} = {wh(t+1), adj(t+2)}; wait for G_t = {wh(t), adj(t+1)}
        if (t + 1 < T) {
            load_wh(buf ^ 1, (t + 1) * BJ);
            if (t + 2 < T) load_adj(buf, (t + 2) * BJ);
            cp_commit();
            cp_wait1();
        } else {
            cp_wait0();
        }

        // ---- MMA(t): 64x256 += E(t) @ Wh(t) ----
#pragma unroll
        for (int kk = 0; kk < BJ; kk += 8) {
            uint32_t a[2][4];
#pragma unroll
            for (int mi = 0; mi < 2; mi++) {
                int r = m0w + mi * 16 + (lane >> 2);
                a[mi][0] = __float_as_uint(s->e[buf][r    ][kk + (lane & 3)    ]);
                a[mi][1] = __float_as_uint(s->e[buf][r + 8][kk + (lane & 3)    ]);
                a[mi][2] = __float_as_uint(s->e[buf][r    ][kk + (lane & 3) + 4]);
                a[mi][3] = __float_as_uint(s->e[buf][r + 8][kk + (lane & 3) + 4]);
            }
            uint32_t bf[8][2];
#pragma unroll
            for (int nj = 0; nj < 8; nj++) {
                int c = n0w + nj * 8 + (lane >> 2);
                bf[nj][0] = __float_as_uint(s->wh[buf][kk + (lane & 3)    ][c]);
                bf[nj][1] = __float_as_uint(s->wh[buf][kk + (lane & 3) + 4][c]);
            }
#pragma unroll
            for (int mi = 0; mi < 2; mi++)
#pragma unroll
                for (int nj = 0; nj < 8; nj++)
                    mma_tf32(acc[mi][nj], a[mi], bf[nj]);
        }

        // ---- E-compute(t+1) -> e[buf^1] (overlaps HMMA drain) ----
        if (t + 1 < T) compute_e(buf ^ 1, buf ^ 1, (t + 1) * BJ);

        __syncthreads();   // single barrier per iteration
    }

    // rowsum reduce: 4 threads (same erow) hold partials
    esum += __shfl_xor_sync(0xffffffff, esum, 1);
    esum += __shfl_xor_sync(0xffffffff, esum, 2);
    if ((tid & 3) == 0) s->rs[erow] = esum;
    __syncthreads();

    // epilogue: normalize, hybrid-precise ELU, store
#pragma unroll
    for (int mi = 0; mi < 2; mi++) {
        int r0 = m0w + mi * 16 + (lane >> 2);
        float inv0 = 1.f / s->rs[r0];
        float inv1 = 1.f / s->rs[r0 + 8];
#pragma unroll
        for (int nj = 0; nj < 8; nj++) {
            int col = n0w + nj * 8 + 2 * (lane & 3);
            float v0 = elu(acc[mi][nj][0] * inv0);
            float v1 = elu(acc[mi][nj][1] * inv0);
            float v2 = elu(acc[mi][nj][2] * inv1);
            float v3 = elu(acc[mi][nj][3] * inv1);
            size_t base = (size_t)(b * NNODE + i0 + r0) * FEAT + col;
            *(float2*)(out + base)            = make_float2(v0, v1);
            *(float2*)(out + base + 8 * FEAT) = make_float2(v2, v3);
        }
    }
}

// ============================================================================
// launch
// ============================================================================
extern "C" void kernel_launch(void* const* d_in, const int* in_sizes, int n_in,
                              void* d_out, int out_size)
{
    const float* h   = (const float*)d_in[0];
    const int*   adj = (const int*)  d_in[1];
    const float* W   = (const float*)d_in[2];
    const float* a   = (const float*)d_in[3];
    float*       out = (float*)d_out;

    // zero si/sj accumulators (doubles, filled by k_wh_tc epilogue atomics)
    void* p_si = nullptr;
    void* p_sj = nullptr;
    cudaGetSymbolAddress(&p_si, g_si);
    cudaGetSymbolAddress(&p_sj, g_sj);
    cudaMemsetAsync(p_si, 0, MROWS * sizeof(double));
    cudaMemsetAsync(p_sj, 0, MROWS * sizeof(double));

    // K1: Wh = h @ W^T (tensor cores, tf32) + fused si/sj accumulation
    {
        dim3 grid(FEAT / 128, MROWS / 128);   // (2, 256)
        k_wh_tc<<<grid, 256>>>(h, W, a);
    }
    // K3: fused masked-softmax + attn@Wh + ELU (pipelined, factorized exp)
    {
        cudaFuncSetAttribute(k_fused, cudaFuncAttributeMaxDynamicSharedMemorySize,
                             (int)sizeof(SmemFused));
        dim3 grid(NNODE / BI, BATCH);         // (16, 32)
        k_fused<<<grid, 256, sizeof(SmemFused)>>>(adj, out);
    }
}

// round 14
// speedup vs baseline: 1.1818x; 1.0237x over previous
#include <cuda_runtime.h>
#include <cuda_bf16.h>
#include <math.h>
#include <stdint.h>

// Problem constants
#define BATCH 32
#define NNODE 1024
#define FEAT  256           // IN_F == OUT_F == 256
#define MROWS (BATCH*NNODE) // 32768
#define ALPHA_LRELU 0.2f

// ---------------- scratch (device globals; no runtime allocation) -----------
__device__ float g_Wh[(size_t)MROWS * FEAT];                 // 32 MB (tf32-rounded)
__device__ float g_si[MROWS];
__device__ float g_sj[MROWS];

// ---------------- helpers ----------------------------------------------------
__device__ __forceinline__ float to_tf32(float x) {
    float r;
    asm("cvt.rna.tf32.f32 %0, %1;" : "=f"(r) : "f"(x));
    return r;
}

__device__ __forceinline__ void cp16(uint32_t dst, const void* src) {
    asm volatile("cp.async.cg.shared.global [%0], [%1], 16;\n" :: "r"(dst), "l"(src));
}
__device__ __forceinline__ void cp_commit() {
    asm volatile("cp.async.commit_group;\n" ::);
}
__device__ __forceinline__ void cp_wait1() {
    asm volatile("cp.async.wait_group 1;\n" ::);
}
__device__ __forceinline__ void cp_wait0() {
    asm volatile("cp.async.wait_group 0;\n" ::);
}

__device__ __forceinline__ void mma_tf32(float* c, const uint32_t* a, const uint32_t* b) {
    asm volatile(
        "mma.sync.aligned.m16n8k8.row.col.f32.tf32.tf32.f32 "
        "{%0,%1,%2,%3}, {%4,%5,%6,%7}, {%8,%9}, {%0,%1,%2,%3};"
        : "+f"(c[0]), "+f"(c[1]), "+f"(c[2]), "+f"(c[3])
        : "r"(a[0]), "r"(a[1]), "r"(a[2]), "r"(a[3]), "r"(b[0]), "r"(b[1]));
}

// precise-cheap expm1 for v <= 0: Taylor near 0, expf-1 elsewhere.
__device__ __forceinline__ float elu_neg(float v) {
    float em = __expf(v) - 1.f;
    float ta = v + 0.5f * v * v * (1.f + 0.33333333f * v);   // v + v^2/2 + v^3/6
    return (v > -0.0625f) ? ta : em;
}
__device__ __forceinline__ float elu(float v) {
    return (v > 0.f) ? v : elu_neg(v);
}

// ============================================================================
// K1: Wh[m,o] = sum_k h[m,k] * W[o,k]   (NT GEMM, M=32768, N=256, K=256)
// tf32 mma with rna cvt on fragments, 128x128 tile, BK=32 (8 iterations).
// Epilogue accumulates si/sj partials via quad-reduced float atomicAdd.
// ============================================================================
__global__ __launch_bounds__(256, 2) void k_wh_tc(const float* __restrict__ A,
                                                  const float* __restrict__ Bw,
                                                  const float* __restrict__ avec)
{
    __shared__ float sA[2][128][36];   // 128 rows x 32 k (+4 pad)
    __shared__ float sW[2][128][36];

    const int m0 = blockIdx.y * 128;
    const int n0 = blockIdx.x * 128;
    const int tid  = threadIdx.x;
    const int lane = tid & 31;
    const int wid  = tid >> 5;
    const int m0w  = (wid >> 2) * 64;   // 0 or 64
    const int n0w  = (wid & 3) * 32;    // 0,32,64,96

    float acc[4][4][4];
#pragma unroll
    for (int i = 0; i < 4; i++)
#pragma unroll
        for (int j = 0; j < 4; j++)
#pragma unroll
            for (int r = 0; r < 4; r++) acc[i][j][r] = 0.f;

    const int T = FEAT / 32;  // 8

    auto load_stage = [&](int buf, int k0) {
#pragma unroll
        for (int it = 0; it < 4; it++) {
            int f   = tid + it * 256;    // 0..1023
            int row = f >> 3;
            int kq  = (f & 7) * 4;
            cp16((uint32_t)__cvta_generic_to_shared(&sA[buf][row][kq]),
                 A + (size_t)(m0 + row) * FEAT + k0 + kq);
            cp16((uint32_t)__cvta_generic_to_shared(&sW[buf][row][kq]),
                 Bw + (size_t)(n0 + row) * FEAT + k0 + kq);
        }
    };

    load_stage(0, 0);
    cp_commit();

    for (int t = 0; t < T; t++) {
        if (t + 1 < T) { load_stage((t + 1) & 1, (t + 1) * 32); cp_commit(); }
        if (t + 1 < T) cp_wait1(); else cp_wait0();
        __syncthreads();

        const int buf = t & 1;
#pragma unroll
        for (int kk = 0; kk < 32; kk += 8) {
            uint32_t a[4][4];
#pragma unroll
            for (int mi = 0; mi < 4; mi++) {
                int r = m0w + mi * 16 + (lane >> 2);
                a[mi][0] = __float_as_uint(to_tf32(sA[buf][r    ][kk + (lane & 3)    ]));
                a[mi][1] = __float_as_uint(to_tf32(sA[buf][r + 8][kk + (lane & 3)    ]));
                a[mi][2] = __float_as_uint(to_tf32(sA[buf][r    ][kk + (lane & 3) + 4]));
                a[mi][3] = __float_as_uint(to_tf32(sA[buf][r + 8][kk + (lane & 3) + 4]));
            }
            uint32_t bf[4][2];
#pragma unroll
            for (int nj = 0; nj < 4; nj++) {
                int c = n0w + nj * 8 + (lane >> 2);
                bf[nj][0] = __float_as_uint(to_tf32(sW[buf][c][kk + (lane & 3)    ]));
                bf[nj][1] = __float_as_uint(to_tf32(sW[buf][c][kk + (lane & 3) + 4]));
            }
#pragma unroll
            for (int mi = 0; mi < 4; mi++)
#pragma unroll
                for (int nj = 0; nj < 4; nj++)
                    mma_tf32(acc[mi][nj], a[mi], bf[nj]);
        }
        __syncthreads();
    }

    // preload a1/a2 for this thread's 8 columns
    float a1v[8], a2v[8];
#pragma unroll
    for (int nj = 0; nj < 4; nj++) {
        int c = n0 + n0w + nj * 8 + 2 * (lane & 3);
        a1v[nj * 2]     = avec[c];
        a1v[nj * 2 + 1] = avec[c + 1];
        a2v[nj * 2]     = avec[FEAT + c];
        a2v[nj * 2 + 1] = avec[FEAT + c + 1];
    }

#pragma unroll
    for (int mi = 0; mi < 4; mi++) {
        int row = m0 + m0w + mi * 16 + (lane >> 2);
        float p1_lo = 0.f, p2_lo = 0.f, p1_hi = 0.f, p2_hi = 0.f;
#pragma unroll
        for (int nj = 0; nj < 4; nj++) {
            int col = n0 + n0w + nj * 8 + 2 * (lane & 3);
            float v0 = to_tf32(acc[mi][nj][0]);
            float v1 = to_tf32(acc[mi][nj][1]);
            float v2 = to_tf32(acc[mi][nj][2]);
            float v3 = to_tf32(acc[mi][nj][3]);
            *(float2*)(g_Wh + (size_t)row * FEAT + col)       = make_float2(v0, v1);
            *(float2*)(g_Wh + (size_t)(row + 8) * FEAT + col) = make_float2(v2, v3);
            p1_lo += v0 * a1v[nj * 2] + v1 * a1v[nj * 2 + 1];
            p2_lo += v0 * a2v[nj * 2] + v1 * a2v[nj * 2 + 1];
            p1_hi += v2 * a1v[nj * 2] + v3 * a1v[nj * 2 + 1];
            p2_hi += v2 * a2v[nj * 2] + v3 * a2v[nj * 2 + 1];
        }
        // quad reduce (lanes sharing the same rows, different col pairs)
        p1_lo += __shfl_xor_sync(0xffffffff, p1_lo, 1);
        p1_lo += __shfl_xor_sync(0xffffffff, p1_lo, 2);
        p2_lo += __shfl_xor_sync(0xffffffff, p2_lo, 1);
        p2_lo += __shfl_xor_sync(0xffffffff, p2_lo, 2);
        p1_hi += __shfl_xor_sync(0xffffffff, p1_hi, 1);
        p1_hi += __shfl_xor_sync(0xffffffff, p1_hi, 2);
        p2_hi += __shfl_xor_sync(0xffffffff, p2_hi, 1);
        p2_hi += __shfl_xor_sync(0xffffffff, p2_hi, 2);
        if ((lane & 3) == 0) {
            atomicAdd(&g_si[row], p1_lo);
            atomicAdd(&g_sj[row], p2_lo);
            atomicAdd(&g_si[row + 8], p1_hi);
            atomicAdd(&g_sj[row + 8], p2_hi);
        }
    }
}

// ============================================================================
// K3 (fused, pipelined, factorized-exp) — R8's PROVEN shell:
//   E[i,j] = adj ? ( pi*pj >= 1 ? pi*pj : qi*qj ) : 0
//   O[i,:] = (E @ Wh[b]) / rowsum(E), then ELU.
// adj via cp.async smem; vectorized LDS.128 adj/pq reads in compute_e.
// BI=64, BJ=32, 256 threads, 2 CTAs/SM. One __syncthreads per j-step.
// ============================================================================
#define BI 64
#define BJ 32

struct SmemFused {
    float  wh[2][BJ][264];   // [k][n] B tiles
    float  e[2][BI][36];     // E tiles, double-buffered
    int    adj[2][BI][BJ];
    float2 pq[NNODE];        // {exp(sj), exp(0.2 sj)}
    float  rs[BI];
};

__global__ __launch_bounds__(256, 2) void k_fused(const int* __restrict__ adj,
                                                  float* __restrict__ out)
{
    extern __shared__ char smem_raw[];
    SmemFused* s = (SmemFused*)smem_raw;

    const int b  = blockIdx.y;
    const int i0 = blockIdx.x * BI;
    const int tid  = threadIdx.x;
    const int lane = tid & 31;
    const int wid  = tid >> 5;
    const int m0w  = (wid >> 2) * 32;   // 0 or 32
    const int n0w  = (wid & 3) * 64;    // 0,64,128,192

    const int*   adjb = adj  + ((size_t)b * NNODE + i0) * NNODE;
    const float* Whb  = g_Wh + (size_t)b * NNODE * FEAT;

    // preamble: pj/qj for this batch (4 per thread), pi/qi for this row
#pragma unroll
    for (int u = 0; u < 4; u++) {
        int j = tid + u * 256;
        float sjv = g_sj[(size_t)b * NNODE + j];
        s->pq[j] = make_float2(__expf(sjv), __expf(ALPHA_LRELU * sjv));
    }
    const int   erow = tid >> 2;            // E row this thread produces
    const int   ecol = (tid & 3) * 8;       // first of 8 E cols
    const float si_r = g_si[(size_t)b * NNODE + i0 + erow];
    const float pi_r = __expf(si_r);
    const float qi_r = __expf(ALPHA_LRELU * si_r);

    float acc[2][8][4];
#pragma unroll
    for (int i = 0; i < 2; i++)
#pragma unroll
        for (int j = 0; j < 8; j++)
#pragma unroll
            for (int r = 0; r < 4; r++) acc[i][j][r] = 0.f;

    float esum = 0.f;

    auto load_adj = [&](int buf, int j0) {
#pragma unroll
        for (int it = 0; it < 2; it++) {
            int f   = tid + it * 256;
            int row = f >> 3;
            int c   = (f & 7) * 4;
            cp16((uint32_t)__cvta_generic_to_shared(&s->adj[buf][row][c]),
                 adjb + (size_t)row * NNODE + j0 + c);
        }
    };
    auto load_wh = [&](int buf, int j0) {
#pragma unroll
        for (int it = 0; it < 8; it++) {
            int f = tid + it * 256;
            int k = f >> 6;
            int c = (f & 63) * 4;
            cp16((uint32_t)__cvta_generic_to_shared(&s->wh[buf][k][c]),
                 Whb + (size_t)(j0 + k) * FEAT + c);
        }
    };

    // E-tile compute (vectorized adj/pq reads)
    auto compute_e = [&](int ebuf, int abuf, int j0) {
        int4 a0 = *(const int4*)&s->adj[abuf][erow][ecol];
        int4 a1 = *(const int4*)&s->adj[abuf][erow][ecol + 4];
        const float4* pq4 = (const float4*)&s->pq[j0 + ecol];
        float4 q0 = pq4[0], q1 = pq4[1], q2 = pq4[2], q3 = pq4[3];
        const int   am[8]  = { a0.x, a0.y, a0.z, a0.w, a1.x, a1.y, a1.z, a1.w };
        const float pjv[8] = { q0.x, q0.z, q1.x, q1.z, q2.x, q2.z, q3.x, q3.z };
        const float qjv[8] = { q0.y, q0.w, q1.y, q1.w, q2.y, q2.w, q3.y, q3.w };
        float ev[8];
#pragma unroll
        for (int u = 0; u < 8; u++) {
            float ep = pi_r * pjv[u];
            float eq = qi_r * qjv[u];
            float e  = (ep >= 1.0f) ? ep : eq;
            e = (am[u] > 0) ? e : 0.f;
            e = __uint_as_float(__float_as_uint(e) & 0xffffe000u);  // tf32 trunc
            esum += e;
            ev[u] = e;
        }
        *(float4*)&s->e[ebuf][erow][ecol]     = make_float4(ev[0], ev[1], ev[2], ev[3]);
        *(float4*)&s->e[ebuf][erow][ecol + 4] = make_float4(ev[4], ev[5], ev[6], ev[7]);
    };

    const int T = NNODE / BJ;  // 32

    // Preamble: G_a = {adj(0)}, G_0 = {wh(0), adj(1)}
    load_adj(0, 0);
    cp_commit();
    load_wh(0, 0);
    load_adj(1, BJ);
    cp_commit();
    cp_wait1();          // adj(0) arrived
    __syncthreads();     // also publishes pq

    compute_e(0, 0, 0);
    __syncthreads();

    for (int t = 0; t < T; t++) {
        const int buf = t & 1;

        // Commit G_{t+1} = {wh(t+1), adj(t+2)}; wait for G_t = {wh(t), adj(t+1)}
        if (t + 1 < T) {
            load_wh(buf ^ 1, (t + 1) * BJ);
            if (t + 2 < T) load_adj(buf, (t + 2) * BJ);
            cp_commit();
            cp_wait1();
        } else {
            cp_wait0();
        }

        // ---- MMA(t): 64x256 += E(t) @ Wh(t) ----
#pragma unroll
        for (int kk = 0; kk < BJ; kk += 8) {
            uint32_t a[2][4];
#pragma unroll
            for (int mi = 0; mi < 2; mi++) {
                int r = m0w + mi * 16 + (lane >> 2);
                a[mi][0] = __float_as_uint(s->e[buf][r    ][kk + (lane & 3)    ]);
                a[mi][1] = __float_as_uint(s->e[buf][r + 8][kk + (lane & 3)    ]);
                a[mi][2] = __float_as_uint(s->e[buf][r    ][kk + (lane & 3) + 4]);
                a[mi][3] = __float_as_uint(s->e[buf][r + 8][kk + (lane & 3) + 4]);
            }
            uint32_t bf[8][2];
#pragma unroll
            for (int nj = 0; nj < 8; nj++) {
                int c = n0w + nj * 8 + (lane >> 2);
                bf[nj][0] = __float_as_uint(s->wh[buf][kk + (lane & 3)    ][c]);
                bf[nj][1] = __float_as_uint(s->wh[buf][kk + (lane & 3) + 4][c]);
            }
#pragma unroll
            for (int mi = 0; mi < 2; mi++)
#pragma unroll
                for (int nj = 0; nj < 8; nj++)
                    mma_tf32(acc[mi][nj], a[mi], bf[nj]);
        }

        // ---- E-compute(t+1) -> e[buf^1] (overlaps HMMA drain) ----
        if (t + 1 < T) compute_e(buf ^ 1, buf ^ 1, (t + 1) * BJ);

        __syncthreads();   // single barrier per iteration
    }

    // rowsum reduce: 4 threads (same erow) hold partials
    esum += __shfl_xor_sync(0xffffffff, esum, 1);
    esum += __shfl_xor_sync(0xffffffff, esum, 2);
    if ((tid & 3) == 0) s->rs[erow] = esum;
    __syncthreads();

    // epilogue: normalize, hybrid-precise ELU, store
#pragma unroll
    for (int mi = 0; mi < 2; mi++) {
        int r0 = m0w + mi * 16 + (lane >> 2);
        float inv0 = 1.f / s->rs[r0];
        float inv1 = 1.f / s->rs[r0 + 8];
#pragma unroll
        for (int nj = 0; nj < 8; nj++) {
            int col = n0w + nj * 8 + 2 * (lane & 3);
            float v0 = elu(acc[mi][nj][0] * inv0);
            float v1 = elu(acc[mi][nj][1] * inv0);
            float v2 = elu(acc[mi][nj][2] * inv1);
            float v3 = elu(acc[mi][nj][3] * inv1);
            size_t base = (size_t)(b * NNODE + i0 + r0) * FEAT + col;
            *(float2*)(out + base)            = make_float2(v0, v1);
            *(float2*)(out + base + 8 * FEAT) = make_float2(v2, v3);
        }
    }
}

// ============================================================================
// launch
// ============================================================================
extern "C" void kernel_launch(void* const* d_in, const int* in_sizes, int n_in,
                              void* d_out, int out_size)
{
    const float* h   = (const float*)d_in[0];
    const int*   adj = (const int*)  d_in[1];
    const float* W   = (const float*)d_in[2];
    const float* a   = (const float*)d_in[3];
    float*       out = (float*)d_out;

    // zero si/sj accumulators (filled by k_wh_tc epilogue atomics)
    void* p_si = nullptr;
    void* p_sj = nullptr;
    cudaGetSymbolAddress(&p_si, g_si);
    cudaGetSymbolAddress(&p_sj, g_sj);
    cudaMemsetAsync(p_si, 0, MROWS * sizeof(float));
    cudaMemsetAsync(p_sj, 0, MROWS * sizeof(float));

    // K1: Wh = h @ W^T (tensor cores, tf32, BK=32) + fused si/sj accumulation
    {
        dim3 grid(FEAT / 128, MROWS / 128);   // (2, 256)
        k_wh_tc<<<grid, 256>>>(h, W, a);
    }
    // K3: fused masked-softmax + attn@Wh + ELU (pipelined, factorized exp)
    {
        cudaFuncSetAttribute(k_fused, cudaFuncAttributeMaxDynamicSharedMemorySize,
                             (int)sizeof(SmemFused));
        dim3 grid(NNODE / BI, BATCH);         // (16, 32)
        k_fused<<<grid, 256, sizeof(SmemFused)>>>(adj, out);
    }
}